// round 4
// baseline (speedup 1.0000x reference)
#include <cuda_runtime.h>

#define N_NODES 100000
#define N_EDGES 1600000
#define D 64

// Scratch (allocation-free rule: device globals). 16B-aligned for float4 atomics.
__device__ __align__(16) float g_accum[N_NODES * D];
__device__ float g_deg[N_NODES];

// ---------------------------------------------------------------------------
// Kernel 1: zero the scratch buffers
// ---------------------------------------------------------------------------
__global__ void zero_kernel() {
    int i = blockIdx.x * blockDim.x + threadIdx.x;
    if (i < N_NODES * (D / 4)) {
        ((float4*)g_accum)[i] = make_float4(0.f, 0.f, 0.f, 0.f);
    }
    if (i < N_NODES) {
        g_deg[i] = 0.f;
    }
}

// ---------------------------------------------------------------------------
// Kernel 2: edge scatter.  16 threads per edge; each thread owns one float4
// chunk of the 64-float feature row.  float4 atomicAdd (RED.128) into accum.
// NOTE: src/dst are int32 (JAX x64-disabled: requested int64 silently -> int32).
// ---------------------------------------------------------------------------
__global__ void __launch_bounds__(256) scatter_kernel(
        const float4* __restrict__ feat4,
        const int* __restrict__ src,
        const int* __restrict__ dst,
        const float* __restrict__ w) {
    long long t = (long long)blockIdx.x * blockDim.x + threadIdx.x;
    int e = (int)(t >> 4);
    int c = (int)(t & 15);
    if (e >= N_EDGES) return;

    // 16 lanes read the same address -> single-sector broadcast load.
    int   s  = src[e];
    int   d  = dst[e];
    float ww = w[e];

    float4 v = feat4[(long long)s * (D / 4) + c];
    v.x *= ww; v.y *= ww; v.z *= ww; v.w *= ww;

    atomicAdd(((float4*)g_accum) + (long long)d * (D / 4) + c, v);
    if (c == 0) atomicAdd(&g_deg[d], 1.0f);
}

// ---------------------------------------------------------------------------
// Kernel 3: out = feat @ Wself^T + (accum/max(deg,1)) @ Wneigh^T + bias
// Block = 128 threads, tile = 32 nodes x 64 cols.
// Thread (tx=t%16, ty=t/16) computes 4 nodes x 4 cols (16 outputs).
// featS/neighS stored transposed [k][node] (stride 33) -> conflict-free.
// Ws/Wn stored [j][k] (stride 65)                      -> conflict-free.
// ---------------------------------------------------------------------------
__global__ void __launch_bounds__(128) out_kernel(
        const float* __restrict__ feat,
        const float* __restrict__ W_neigh,
        const float* __restrict__ W_self,
        const float* __restrict__ bias,
        float* __restrict__ out) {
    __shared__ float featS[D][33];   // [k][node]
    __shared__ float neighS[D][33];  // [k][node]
    __shared__ float Ws[D][65];      // [j][k]
    __shared__ float Wn[D][65];      // [j][k]
    __shared__ float rdeg[32];
    __shared__ float biasS[D];

    const int t = threadIdx.x;          // 0..127
    const int node0 = blockIdx.x * 32;

    if (t < 32) {
        float dg = g_deg[node0 + t];
        rdeg[t] = 1.0f / fmaxf(dg, 1.0f);
    }
    if (t < D) biasS[t] = bias[t];
    __syncthreads();

    // Weights: coalesced read, conflict-free STS (consecutive k).
    for (int idx = t; idx < D * D; idx += 128) {
        int j = idx >> 6, k = idx & 63;
        Ws[j][k] = W_self[idx];
        Wn[j][k] = W_neigh[idx];
    }
    // Feature / neighbor tiles, transposed into smem.
    for (int idx = t; idx < 32 * D; idx += 128) {
        int n = idx >> 6, k = idx & 63;
        featS[k][n]  = feat[(long long)(node0 + n) * D + k];
        neighS[k][n] = g_accum[(long long)(node0 + n) * D + k] * rdeg[n];
    }
    __syncthreads();

    const int tx = t & 15;   // column group: cols tx*4 .. tx*4+3
    const int ty = t >> 4;   // node group:   nodes ty*4 .. ty*4+3

    float acc[4][4];
#pragma unroll
    for (int n = 0; n < 4; n++)
#pragma unroll
        for (int j = 0; j < 4; j++)
            acc[n][j] = biasS[tx * 4 + j];

#pragma unroll 8
    for (int k = 0; k < D; k++) {
        float a[4], c[4], bs[4], bn[4];
#pragma unroll
        for (int n = 0; n < 4; n++) {
            a[n] = featS[k][ty * 4 + n];
            c[n] = neighS[k][ty * 4 + n];
        }
#pragma unroll
        for (int j = 0; j < 4; j++) {
            bs[j] = Ws[tx * 4 + j][k];
            bn[j] = Wn[tx * 4 + j][k];
        }
#pragma unroll
        for (int n = 0; n < 4; n++)
#pragma unroll
            for (int j = 0; j < 4; j++)
                acc[n][j] += a[n] * bs[j] + c[n] * bn[j];
    }

    // Coalesced float4 stores.
    float4* out4 = (float4*)out;
#pragma unroll
    for (int n = 0; n < 4; n++) {
        out4[(long long)(node0 + ty * 4 + n) * (D / 4) + tx] =
            make_float4(acc[n][0], acc[n][1], acc[n][2], acc[n][3]);
    }
}

// ---------------------------------------------------------------------------
// Launch
// ---------------------------------------------------------------------------
extern "C" void kernel_launch(void* const* d_in, const int* in_sizes, int n_in,
                              void* d_out, int out_size) {
    const float* feat = (const float*)d_in[0];
    const int*   src  = (const int*)d_in[1];
    const int*   dst  = (const int*)d_in[2];
    const float* ew   = (const float*)d_in[3];
    const float* Wn   = (const float*)d_in[4];
    const float* Wsf  = (const float*)d_in[5];
    const float* bias = (const float*)d_in[6];
    float* out = (float*)d_out;

    (void)in_sizes; (void)n_in; (void)out_size;

    // 1) zero scratch
    {
        int total = N_NODES * (D / 4);
        int blocks = (total + 255) / 256;
        zero_kernel<<<blocks, 256>>>();
    }
    // 2) edge scatter (E*16 threads, exact multiple of 256)
    {
        long long threads = (long long)N_EDGES * 16;
        int blocks = (int)((threads + 255) / 256);
        scatter_kernel<<<blocks, 256>>>((const float4*)feat, src, dst, ew);
    }
    // 3) output transform
    {
        out_kernel<<<N_NODES / 32, 128>>>(feat, Wn, Wsf, bias, out);
    }
}

// round 5
// speedup vs baseline: 1.0478x; 1.0478x over previous
#include <cuda_runtime.h>

#define N_NODES 100000
#define N_EDGES 1600000
#define D 64
#define SCAN_BLK 1024
#define N_PARTIAL ((N_NODES + SCAN_BLK - 1) / SCAN_BLK)   // 98

// Scratch (allocation-free rule: device globals)
__device__ float g_neigh[N_NODES * D];      // mean-aggregated neighbor features
__device__ int   g_count[N_NODES];
__device__ int   g_off[N_NODES + 1];
__device__ int   g_cursor[N_NODES];
__device__ int   g_partial[128];
__device__ int   g_csr_src[N_EDGES];
__device__ float g_csr_w[N_EDGES];

// ---------------------------------------------------------------------------
// k0: zero degree counts
// ---------------------------------------------------------------------------
__global__ void zero_count_kernel() {
    int i = blockIdx.x * blockDim.x + threadIdx.x;
    if (i < N_NODES) g_count[i] = 0;
}

// ---------------------------------------------------------------------------
// k1: histogram of dst
// ---------------------------------------------------------------------------
__global__ void __launch_bounds__(256) hist_kernel(const int* __restrict__ dst) {
    int e = blockIdx.x * blockDim.x + threadIdx.x;
    if (e < N_EDGES) atomicAdd(&g_count[dst[e]], 1);
}

// ---------------------------------------------------------------------------
// k2a: per-1024-segment sums -> g_partial
// ---------------------------------------------------------------------------
__global__ void __launch_bounds__(256) partial_kernel() {
    __shared__ int wsum[8];
    int t = threadIdx.x;
    int base = blockIdx.x * SCAN_BLK + t * 4;
    int s = 0;
#pragma unroll
    for (int k = 0; k < 4; k++) {
        int idx = base + k;
        if (idx < N_NODES) s += g_count[idx];
    }
    // warp reduce
#pragma unroll
    for (int d = 16; d > 0; d >>= 1) s += __shfl_down_sync(0xFFFFFFFFu, s, d);
    if ((t & 31) == 0) wsum[t >> 5] = s;
    __syncthreads();
    if (t == 0) {
        int tot = 0;
#pragma unroll
        for (int w = 0; w < 8; w++) tot += wsum[w];
        g_partial[blockIdx.x] = tot;
    }
}

// ---------------------------------------------------------------------------
// k2b: exclusive scan of partials (tiny, serial) + write off[N]
// ---------------------------------------------------------------------------
__global__ void scan_partial_kernel() {
    if (threadIdx.x == 0) {
        int run = 0;
        for (int i = 0; i < N_PARTIAL; i++) {
            int v = g_partial[i];
            g_partial[i] = run;
            run += v;
        }
        g_off[N_NODES] = run;   // == N_EDGES
    }
}

// ---------------------------------------------------------------------------
// k2c: per-segment exclusive scan + base -> g_off, g_cursor
// ---------------------------------------------------------------------------
__global__ void __launch_bounds__(256) offsets_kernel() {
    __shared__ int wsum[8];
    __shared__ int wbase[8];
    int t = threadIdx.x;
    int lane = t & 31, wid = t >> 5;
    int base = blockIdx.x * SCAN_BLK + t * 4;

    int c[4];
    int s = 0;
#pragma unroll
    for (int k = 0; k < 4; k++) {
        int idx = base + k;
        c[k] = (idx < N_NODES) ? g_count[idx] : 0;
        s += c[k];
    }
    int own = s;
    // warp inclusive scan
#pragma unroll
    for (int d = 1; d < 32; d <<= 1) {
        int v = __shfl_up_sync(0xFFFFFFFFu, s, d);
        if (lane >= d) s += v;
    }
    if (lane == 31) wsum[wid] = s;
    __syncthreads();
    if (t == 0) {
        int run = 0;
#pragma unroll
        for (int w = 0; w < 8; w++) { wbase[w] = run; run += wsum[w]; }
    }
    __syncthreads();

    int excl = (s - own) + wbase[wid] + g_partial[blockIdx.x];
#pragma unroll
    for (int k = 0; k < 4; k++) {
        int idx = base + k;
        if (idx < N_NODES) {
            g_off[idx] = excl;
            g_cursor[idx] = excl;
        }
        excl += c[k];
    }
}

// ---------------------------------------------------------------------------
// k3: fill CSR bins (src, w) via atomic cursor
// ---------------------------------------------------------------------------
__global__ void __launch_bounds__(256) fill_kernel(const int* __restrict__ src,
                                                   const int* __restrict__ dst,
                                                   const float* __restrict__ w) {
    int e = blockIdx.x * blockDim.x + threadIdx.x;
    if (e >= N_EDGES) return;
    int d = dst[e];
    int p = atomicAdd(&g_cursor[d], 1);
    g_csr_src[p] = src[e];
    g_csr_w[p]   = w[e];
}

// ---------------------------------------------------------------------------
// k4: gather + mean.  One warp per node; lane owns 2 columns (float2).
// 2-edge unroll with dual accumulators for MLP.
// ---------------------------------------------------------------------------
__global__ void __launch_bounds__(256) gather_kernel(const float2* __restrict__ feat2) {
    int node = blockIdx.x * 8 + (threadIdx.x >> 5);
    if (node >= N_NODES) return;
    int lane = threadIdx.x & 31;

    int beg = g_off[node];
    int end = g_off[node + 1];

    float2 a0 = make_float2(0.f, 0.f);
    float2 a1 = make_float2(0.f, 0.f);

    int i = beg;
    for (; i + 1 < end; i += 2) {
        int   s0 = g_csr_src[i];
        int   s1 = g_csr_src[i + 1];
        float w0 = g_csr_w[i];
        float w1 = g_csr_w[i + 1];
        float2 v0 = feat2[(long long)s0 * (D / 2) + lane];
        float2 v1 = feat2[(long long)s1 * (D / 2) + lane];
        a0.x += v0.x * w0; a0.y += v0.y * w0;
        a1.x += v1.x * w1; a1.y += v1.y * w1;
    }
    if (i < end) {
        int   s0 = g_csr_src[i];
        float w0 = g_csr_w[i];
        float2 v0 = feat2[(long long)s0 * (D / 2) + lane];
        a0.x += v0.x * w0; a0.y += v0.y * w0;
    }

    float rdeg = 1.0f / fmaxf((float)(end - beg), 1.0f);
    float2 r = make_float2((a0.x + a1.x) * rdeg, (a0.y + a1.y) * rdeg);
    ((float2*)g_neigh)[(long long)node * (D / 2) + lane] = r;
}

// ---------------------------------------------------------------------------
// k5: out = feat @ Wself^T + neigh @ Wneigh^T + bias
// Block = 128 threads, tile = 32 nodes x 64 cols; 4x4 register tile / thread.
// ---------------------------------------------------------------------------
__global__ void __launch_bounds__(128) out_kernel(
        const float* __restrict__ feat,
        const float* __restrict__ W_neigh,
        const float* __restrict__ W_self,
        const float* __restrict__ bias,
        float* __restrict__ out) {
    __shared__ float featS[D][33];   // [k][node]
    __shared__ float neighS[D][33];  // [k][node]
    __shared__ float Ws[D][65];      // [j][k]
    __shared__ float Wn[D][65];      // [j][k]
    __shared__ float biasS[D];

    const int t = threadIdx.x;
    const int node0 = blockIdx.x * 32;

    if (t < D) biasS[t] = bias[t];

    for (int idx = t; idx < D * D; idx += 128) {
        int j = idx >> 6, k = idx & 63;
        Ws[j][k] = W_self[idx];
        Wn[j][k] = W_neigh[idx];
    }
    for (int idx = t; idx < 32 * D; idx += 128) {
        int n = idx >> 6, k = idx & 63;
        featS[k][n]  = feat[(long long)(node0 + n) * D + k];
        neighS[k][n] = g_neigh[(long long)(node0 + n) * D + k];
    }
    __syncthreads();

    const int tx = t & 15;   // cols tx*4 .. tx*4+3
    const int ty = t >> 4;   // nodes ty*4 .. ty*4+3

    float acc[4][4];
#pragma unroll
    for (int n = 0; n < 4; n++)
#pragma unroll
        for (int j = 0; j < 4; j++)
            acc[n][j] = biasS[tx * 4 + j];

#pragma unroll 8
    for (int k = 0; k < D; k++) {
        float a[4], c[4], bs[4], bn[4];
#pragma unroll
        for (int n = 0; n < 4; n++) {
            a[n] = featS[k][ty * 4 + n];
            c[n] = neighS[k][ty * 4 + n];
        }
#pragma unroll
        for (int j = 0; j < 4; j++) {
            bs[j] = Ws[tx * 4 + j][k];
            bn[j] = Wn[tx * 4 + j][k];
        }
#pragma unroll
        for (int n = 0; n < 4; n++)
#pragma unroll
            for (int j = 0; j < 4; j++)
                acc[n][j] += a[n] * bs[j] + c[n] * bn[j];
    }

    float4* out4 = (float4*)out;
#pragma unroll
    for (int n = 0; n < 4; n++) {
        out4[(long long)(node0 + ty * 4 + n) * (D / 4) + tx] =
            make_float4(acc[n][0], acc[n][1], acc[n][2], acc[n][3]);
    }
}

// ---------------------------------------------------------------------------
// Launch
// ---------------------------------------------------------------------------
extern "C" void kernel_launch(void* const* d_in, const int* in_sizes, int n_in,
                              void* d_out, int out_size) {
    const float* feat = (const float*)d_in[0];
    const int*   src  = (const int*)d_in[1];
    const int*   dst  = (const int*)d_in[2];
    const float* ew   = (const float*)d_in[3];
    const float* Wn   = (const float*)d_in[4];
    const float* Wsf  = (const float*)d_in[5];
    const float* bias = (const float*)d_in[6];
    float* out = (float*)d_out;

    (void)in_sizes; (void)n_in; (void)out_size;

    const int EB = (N_EDGES + 255) / 256;     // 6250

    zero_count_kernel<<<(N_NODES + 255) / 256, 256>>>();
    hist_kernel<<<EB, 256>>>(dst);
    partial_kernel<<<N_PARTIAL, 256>>>();
    scan_partial_kernel<<<1, 32>>>();
    offsets_kernel<<<N_PARTIAL, 256>>>();
    fill_kernel<<<EB, 256>>>(src, dst, ew);
    gather_kernel<<<(N_NODES + 7) / 8, 256>>>((const float2*)feat);
    out_kernel<<<N_NODES / 32, 128>>>(feat, Wn, Wsf, bias, out);
}

// round 6
// speedup vs baseline: 1.3041x; 1.2446x over previous
#include <cuda_runtime.h>

#define N_NODES 100000
#define N_EDGES 1600000
#define D 64
#define SCAN_BLK 1024
#define N_PARTIAL ((N_NODES + SCAN_BLK - 1) / SCAN_BLK)   // 98

typedef unsigned long long u64;

// Scratch (allocation-free rule: device globals)
__device__ float g_neigh[N_NODES * D];
__device__ int   g_count[N_NODES];
__device__ int   g_off[N_NODES + 1];
__device__ int   g_cursor[N_NODES];
__device__ int   g_partial[128];
__device__ int   g_csr_src[N_EDGES];
__device__ float g_csr_w[N_EDGES];

// ---- packed fp32x2 helpers (sm_103a FFMA2) --------------------------------
__device__ __forceinline__ void ffma2(u64& d, u64 a, u64 b) {
    asm("fma.rn.f32x2 %0, %1, %2, %0;" : "+l"(d) : "l"(a), "l"(b));
}
__device__ __forceinline__ u64 dup2(float x) {
    u64 r; asm("mov.b64 %0, {%1, %1};" : "=l"(r) : "f"(x)); return r;
}
__device__ __forceinline__ void unpack2(float& lo, float& hi, u64 v) {
    asm("mov.b64 {%0, %1}, %2;" : "=f"(lo), "=f"(hi) : "l"(v));
}

// ---------------------------------------------------------------------------
// k0: zero degree counts
// ---------------------------------------------------------------------------
__global__ void zero_count_kernel() {
    int i = blockIdx.x * blockDim.x + threadIdx.x;
    if (i < N_NODES) g_count[i] = 0;
}

// ---------------------------------------------------------------------------
// k1: histogram of dst
// ---------------------------------------------------------------------------
__global__ void __launch_bounds__(256) hist_kernel(const int* __restrict__ dst) {
    int e = blockIdx.x * blockDim.x + threadIdx.x;
    if (e < N_EDGES) atomicAdd(&g_count[dst[e]], 1);
}

// ---------------------------------------------------------------------------
// k2a: per-1024-segment sums -> g_partial
// ---------------------------------------------------------------------------
__global__ void __launch_bounds__(256) partial_kernel() {
    __shared__ int wsum[8];
    int t = threadIdx.x;
    int base = blockIdx.x * SCAN_BLK + t * 4;
    int s = 0;
#pragma unroll
    for (int k = 0; k < 4; k++) {
        int idx = base + k;
        if (idx < N_NODES) s += g_count[idx];
    }
#pragma unroll
    for (int d = 16; d > 0; d >>= 1) s += __shfl_down_sync(0xFFFFFFFFu, s, d);
    if ((t & 31) == 0) wsum[t >> 5] = s;
    __syncthreads();
    if (t == 0) {
        int tot = 0;
#pragma unroll
        for (int w = 0; w < 8; w++) tot += wsum[w];
        g_partial[blockIdx.x] = tot;
    }
}

// ---------------------------------------------------------------------------
// k2b: PARALLEL exclusive scan of 98 partials (one 128-thread block)
// ---------------------------------------------------------------------------
__global__ void __launch_bounds__(128) scan_partial_kernel() {
    __shared__ int wtot[4];
    __shared__ int wbase[4];
    int t = threadIdx.x;
    int lane = t & 31, wid = t >> 5;
    int v = (t < N_PARTIAL) ? g_partial[t] : 0;
    int s = v;
#pragma unroll
    for (int d = 1; d < 32; d <<= 1) {
        int u = __shfl_up_sync(0xFFFFFFFFu, s, d);
        if (lane >= d) s += u;
    }
    if (lane == 31) wtot[wid] = s;
    __syncthreads();
    if (t == 0) {
        int run = 0;
#pragma unroll
        for (int w = 0; w < 4; w++) { wbase[w] = run; run += wtot[w]; }
    }
    __syncthreads();
    int excl = (s - v) + wbase[wid];
    if (t < N_PARTIAL) g_partial[t] = excl;
    if (t == N_PARTIAL - 1) g_off[N_NODES] = excl + v;
}

// ---------------------------------------------------------------------------
// k2c: per-segment exclusive scan + base -> g_off, g_cursor
// ---------------------------------------------------------------------------
__global__ void __launch_bounds__(256) offsets_kernel() {
    __shared__ int wsum[8];
    __shared__ int wbase[8];
    int t = threadIdx.x;
    int lane = t & 31, wid = t >> 5;
    int base = blockIdx.x * SCAN_BLK + t * 4;

    int c[4];
    int s = 0;
#pragma unroll
    for (int k = 0; k < 4; k++) {
        int idx = base + k;
        c[k] = (idx < N_NODES) ? g_count[idx] : 0;
        s += c[k];
    }
    int own = s;
#pragma unroll
    for (int d = 1; d < 32; d <<= 1) {
        int v = __shfl_up_sync(0xFFFFFFFFu, s, d);
        if (lane >= d) s += v;
    }
    if (lane == 31) wsum[wid] = s;
    __syncthreads();
    if (t == 0) {
        int run = 0;
#pragma unroll
        for (int w = 0; w < 8; w++) { wbase[w] = run; run += wsum[w]; }
    }
    __syncthreads();

    int excl = (s - own) + wbase[wid] + g_partial[blockIdx.x];
#pragma unroll
    for (int k = 0; k < 4; k++) {
        int idx = base + k;
        if (idx < N_NODES) {
            g_off[idx] = excl;
            g_cursor[idx] = excl;
        }
        excl += c[k];
    }
}

// ---------------------------------------------------------------------------
// k3: fill CSR bins (src, w)
// ---------------------------------------------------------------------------
__global__ void __launch_bounds__(256) fill_kernel(const int* __restrict__ src,
                                                   const int* __restrict__ dst,
                                                   const float* __restrict__ w) {
    int e = blockIdx.x * blockDim.x + threadIdx.x;
    if (e >= N_EDGES) return;
    int d = dst[e];
    int p = atomicAdd(&g_cursor[d], 1);
    g_csr_src[p] = src[e];
    g_csr_w[p]   = w[e];
}

// ---------------------------------------------------------------------------
// k4: gather + mean.  One warp per node; lane owns 2 columns (float2).
// ---------------------------------------------------------------------------
__global__ void __launch_bounds__(256) gather_kernel(const float2* __restrict__ feat2) {
    int node = blockIdx.x * 8 + (threadIdx.x >> 5);
    if (node >= N_NODES) return;
    int lane = threadIdx.x & 31;

    int beg = g_off[node];
    int end = g_off[node + 1];

    float2 a0 = make_float2(0.f, 0.f);
    float2 a1 = make_float2(0.f, 0.f);

    int i = beg;
    for (; i + 1 < end; i += 2) {
        int   s0 = g_csr_src[i];
        int   s1 = g_csr_src[i + 1];
        float w0 = g_csr_w[i];
        float w1 = g_csr_w[i + 1];
        float2 v0 = feat2[(long long)s0 * (D / 2) + lane];
        float2 v1 = feat2[(long long)s1 * (D / 2) + lane];
        a0.x += v0.x * w0; a0.y += v0.y * w0;
        a1.x += v1.x * w1; a1.y += v1.y * w1;
    }
    if (i < end) {
        int   s0 = g_csr_src[i];
        float w0 = g_csr_w[i];
        float2 v0 = feat2[(long long)s0 * (D / 2) + lane];
        a0.x += v0.x * w0; a0.y += v0.y * w0;
    }

    float rdeg = 1.0f / fmaxf((float)(end - beg), 1.0f);
    float2 r = make_float2((a0.x + a1.x) * rdeg, (a0.y + a1.y) * rdeg);
    ((float2*)g_neigh)[(long long)node * (D / 2) + lane] = r;
}

// ---------------------------------------------------------------------------
// k5: out = feat @ Wself^T + neigh @ Wneigh^T + bias     (FFMA2 path)
// Block: 128 threads, tile 128 nodes x 64 cols.
// Thread (jg = t&7, ng = t>>3): cols {jg + 8j, j=0..7}, nodes ng*8..+7
// packed as 4 adjacent-node pairs in f32x2 registers.
// featS/neighS: [k][node], stride 130 (even -> LDS.64 node pairs).
// WsT/WnT:      [k][j],   stride 65  (conflict-free both ways).
// ---------------------------------------------------------------------------
#define BN 130
__global__ void __launch_bounds__(128) out_kernel(
        const float* __restrict__ feat,
        const float* __restrict__ W_neigh,
        const float* __restrict__ W_self,
        const float* __restrict__ bias,
        float* __restrict__ out) {
    __shared__ float featS[D][BN];
    __shared__ float neighS[D][BN];
    __shared__ float WsT[D][65];
    __shared__ float WnT[D][65];
    __shared__ float biasS[D];

    const int t = threadIdx.x;
    const long long node0 = (long long)blockIdx.x * 128;

    if (t < D) biasS[t] = bias[t];

    // Weights transposed into [k][j] (conflict-free STS: bank = (k + j) % 32)
    for (int idx = t; idx < D * D; idx += 128) {
        int j = idx >> 6, k = idx & 63;
        WsT[k][j] = W_self[idx];
        WnT[k][j] = W_neigh[idx];
    }
    // Node tiles transposed into [k][n]; zero-fill tail nodes.
    for (int idx = t; idx < 128 * D; idx += 128) {
        int n = idx >> 6, k = idx & 63;
        long long node = node0 + n;
        float fv = 0.f, nv = 0.f;
        if (node < N_NODES) {
            fv = feat[node * D + k];
            nv = g_neigh[node * D + k];
        }
        featS[k][n]  = fv;
        neighS[k][n] = nv;
    }
    __syncthreads();

    const int jg = t & 7;    // col lane: cols jg + 8*j
    const int ng = t >> 3;   // node group: nodes ng*8 .. ng*8+7

    u64 acc[4][8];
#pragma unroll
    for (int j = 0; j < 8; j++) {
        u64 b = dup2(biasS[jg + 8 * j]);
#pragma unroll
        for (int np = 0; np < 4; np++) acc[np][j] = b;
    }

#pragma unroll 2
    for (int k = 0; k < D; k++) {
        u64 a2[4], c2[4];
#pragma unroll
        for (int np = 0; np < 4; np++) {
            a2[np] = *reinterpret_cast<const u64*>(&featS[k][ng * 8 + 2 * np]);
            c2[np] = *reinterpret_cast<const u64*>(&neighS[k][ng * 8 + 2 * np]);
        }
        u64 bs2[8], bn2[8];
#pragma unroll
        for (int j = 0; j < 8; j++) {
            bs2[j] = dup2(WsT[k][jg + 8 * j]);
            bn2[j] = dup2(WnT[k][jg + 8 * j]);
        }
#pragma unroll
        for (int np = 0; np < 4; np++)
#pragma unroll
            for (int j = 0; j < 8; j++) {
                ffma2(acc[np][j], a2[np], bs2[j]);
                ffma2(acc[np][j], c2[np], bn2[j]);
            }
    }

    // Stores: node pairs unpacked, cols jg + 8j.
#pragma unroll
    for (int np = 0; np < 4; np++) {
        long long nA = node0 + ng * 8 + 2 * np;
        long long nB = nA + 1;
        bool okA = nA < N_NODES, okB = nB < N_NODES;
#pragma unroll
        for (int j = 0; j < 8; j++) {
            float lo, hi;
            unpack2(lo, hi, acc[np][j]);
            int col = jg + 8 * j;
            if (okA) out[nA * D + col] = lo;
            if (okB) out[nB * D + col] = hi;
        }
    }
}

// ---------------------------------------------------------------------------
// Launch
// ---------------------------------------------------------------------------
extern "C" void kernel_launch(void* const* d_in, const int* in_sizes, int n_in,
                              void* d_out, int out_size) {
    const float* feat = (const float*)d_in[0];
    const int*   src  = (const int*)d_in[1];
    const int*   dst  = (const int*)d_in[2];
    const float* ew   = (const float*)d_in[3];
    const float* Wn   = (const float*)d_in[4];
    const float* Wsf  = (const float*)d_in[5];
    const float* bias = (const float*)d_in[6];
    float* out = (float*)d_out;

    (void)in_sizes; (void)n_in; (void)out_size;

    const int EB = (N_EDGES + 255) / 256;     // 6250

    zero_count_kernel<<<(N_NODES + 255) / 256, 256>>>();
    hist_kernel<<<EB, 256>>>(dst);
    partial_kernel<<<N_PARTIAL, 256>>>();
    scan_partial_kernel<<<1, 128>>>();
    offsets_kernel<<<N_PARTIAL, 256>>>();
    fill_kernel<<<EB, 256>>>(src, dst, ew);
    gather_kernel<<<(N_NODES + 7) / 8, 256>>>((const float2*)feat);
    out_kernel<<<(N_NODES + 127) / 128, 128>>>(feat, Wn, Wsf, bias, out);
}